// round 14
// baseline (speedup 1.0000x reference)
#include <cuda_runtime.h>
#include <cuda_bf16.h>
#include <math.h>
#include <stdint.h>

#define BDIM 16
#define LDIM 1024
#define DDIM 1024
#define KDIM 3
#define MROWS (BDIM * LDIM)          // 16384
#define N1 DDIM                      // conv GEMM N
#define K1 (KDIM * DDIM)             // conv GEMM K = 3072
#define N2 (3 * DDIM)                // U GEMM N = 3072
#define K2 DDIM                      // U GEMM K = 1024

// ---------------- scratch (allocation-free per harness rules) ----------------
__device__ float g_wc[(size_t)N1 * K1];              // conv weights [o][k*D+i], tf32-rounded
__device__ float g_ws[(size_t)N2 * K2];              // sru weights  [e][kin],  tf32-rounded
__device__ float g_xr[(size_t)MROWS * DDIM];         // x, tf32-rounded
__device__ float g_cnn[(size_t)MROWS * DDIM];        // cnn_out   [b*L+l][D]
__device__ float g_normed[(size_t)MROWS * DDIM];     // layernorm out (tf32-rounded)
__device__ float g_U[(size_t)MROWS * N2];            // SRU preact [b*L+l][3D]

// ======================= small helpers ======================================
__device__ __forceinline__ uint32_t smem_u32(const void* p) {
    uint32_t a;
    asm("{ .reg .u64 t; cvta.to.shared.u64 t, %1; cvt.u32.u64 %0, t; }"
        : "=r"(a) : "l"(p));
    return a;
}
__device__ __forceinline__ void ldsm_x4(uint32_t* r, uint32_t addr) {
    asm volatile("ldmatrix.sync.aligned.m8n8.x4.shared.b16 {%0,%1,%2,%3}, [%4];"
                 : "=r"(r[0]), "=r"(r[1]), "=r"(r[2]), "=r"(r[3]) : "r"(addr));
}
__device__ __forceinline__ void ldsm_x2(uint32_t* r, uint32_t addr) {
    asm volatile("ldmatrix.sync.aligned.m8n8.x2.shared.b16 {%0,%1}, [%2];"
                 : "=r"(r[0]), "=r"(r[1]) : "r"(addr));
}
__device__ __forceinline__ void mma_tf32(float* c, const uint32_t* a, const uint32_t* b) {
    asm volatile("mma.sync.aligned.m16n8k8.row.col.f32.tf32.tf32.f32 "
                 "{%0,%1,%2,%3}, {%4,%5,%6,%7}, {%8,%9}, {%0,%1,%2,%3};"
                 : "+f"(c[0]), "+f"(c[1]), "+f"(c[2]), "+f"(c[3])
                 : "r"(a[0]), "r"(a[1]), "r"(a[2]), "r"(a[3]), "r"(b[0]), "r"(b[1]));
}
__device__ __forceinline__ uint32_t f2tf32(float f) {
    uint32_t r;
    asm("cvt.rna.tf32.f32 %0, %1;" : "=r"(r) : "f"(f));
    return r;
}
__device__ __forceinline__ void cp_async16(uint32_t dst, const void* src) {
    asm volatile("cp.async.cg.shared.global [%0], [%1], 16;"
                 :: "r"(dst), "l"(src) : "memory");
}
__device__ __forceinline__ void cp_async16z(uint32_t dst, const void* src, int sz) {
    asm volatile("cp.async.cg.shared.global [%0], [%1], 16, %2;"
                 :: "r"(dst), "l"(src), "r"(sz) : "memory");
}
__device__ __forceinline__ void cp_commit() {
    asm volatile("cp.async.commit_group;" ::: "memory");
}
template <int N>
__device__ __forceinline__ void cp_wait() {
    asm volatile("cp.async.wait_group %0;" :: "n"(N) : "memory");
}

// ======================= repack / pre-round kernels ==========================
__global__ void repack_conv_kernel(const float* __restrict__ conv_w) {
    int idx = blockIdx.x * blockDim.x + threadIdx.x;
    if (idx >= N1 * K1) return;
    int o = idx / K1;
    int kk = idx % K1;
    int k = kk >> 10, i = kk & (DDIM - 1);
    float w = conv_w[((size_t)o * DDIM + i) * KDIM + k];
    g_wc[idx] = __uint_as_float(f2tf32(w));
}
__global__ void repack_sru_kernel(const float* __restrict__ sru_w) {
    int idx = blockIdx.x * blockDim.x + threadIdx.x;
    if (idx >= N2 * K2) return;
    int e = idx / K2;
    int kin = idx & (K2 - 1);
    float w = sru_w[(size_t)kin * N2 + e];
    g_ws[idx] = __uint_as_float(f2tf32(w));
}
__global__ void round_x_kernel(const float* __restrict__ x) {
    int idx = blockIdx.x * blockDim.x + threadIdx.x;
    float4 v = reinterpret_cast<const float4*>(x)[idx];
    uint4 t = make_uint4(f2tf32(v.x), f2tf32(v.y), f2tf32(v.z), f2tf32(v.w));
    reinterpret_cast<uint4*>(g_xr)[idx] = t;
}

// ======================= mma.sync tf32 GEMM (cp.async loader, 2-stage) =======
// C[M,NTOT] = A[M,KTOT] * W^T  (A, W tf32-rounded fp32 in gmem; W [NTOT][KTOT])
// CONV: A virtual — row m=(b*L+l), col kk=(k*D+i) -> xr[(m+k-2)*D+i], 0 if l+k<2
// CTA tile 128x128, K-chunk 32, 8 warps (2m x 4n), warp tile 64x32.
// cp.async direct GMEM->SMEM (no LDG read wavefronts through L1TEX), 2-stage,
// wait<0>+ONE barrier per iter; (256,2) keeps 128 regs & 2 CTAs/SM.
static constexpr int RSF = 36;                         // floats per smem row (32+4 pad)
static constexpr int RSB = RSF * 4;                    // 144 bytes
static constexpr int MAT_BYTES = 128 * RSB;            // 18432 per matrix
static constexpr int STAGE_BYTES = 2 * MAT_BYTES;      // A + B
static constexpr int GEMM_SMEM = 2 * STAGE_BYTES;      // 73728 B

template <bool CONV, int NTOT, int KTOT>
__global__ void __launch_bounds__(256, 2) mma_gemm_kernel(
    const float* __restrict__ Af,
    const float* __restrict__ W,
    const float* __restrict__ bias, float* __restrict__ C)
{
    extern __shared__ char smem[];
    const uint32_t s0 = smem_u32(smem);

    const int tid = threadIdx.x;
    const int wid = tid >> 5;
    const int lane = tid & 31;
    const int wm = wid >> 2;                 // 0..1
    const int wn = wid & 3;                  // 0..3
    const int m0 = blockIdx.y * 128;
    const int n0 = blockIdx.x * 128;
    constexpr int NIT = KTOT / 32;

    const int lr = tid >> 1;                 // loader row 0..127
    const int colf = (tid & 1) * 16;         // loader col base (floats)

    float acc[4][4][4];
#pragma unroll
    for (int mi = 0; mi < 4; mi++)
#pragma unroll
        for (int ni = 0; ni < 4; ni++)
#pragma unroll
            for (int r = 0; r < 4; r++) acc[mi][ni][r] = 0.f;

    auto issue_stage = [&](int it) {
        const int kk0 = it * 32;
        const int st = it & 1;
        const uint32_t dA = s0 + (uint32_t)st * STAGE_BYTES + (uint32_t)(lr * RSF + colf) * 4;
        const uint32_t dB = dA + MAT_BYTES;
        const float* srcA;
        int szA = 16;
        if (CONV) {
            const int kblk = kk0 >> 10;
            const int i0 = (kk0 & (DDIM - 1)) + colf;
            const int m = m0 + lr;
            const int l = m & (LDIM - 1);
            int row = m + kblk - 2;
            if (l + kblk < 2) { szA = 0; row = m; }
            srcA = Af + ((size_t)row * DDIM + i0);
        } else {
            srcA = Af + (size_t)(m0 + lr) * KTOT + kk0 + colf;
        }
        const float* srcB = W + (size_t)(n0 + lr) * KTOT + kk0 + colf;
#pragma unroll
        for (int j = 0; j < 4; j++) {
            cp_async16z(dA + j * 16, srcA + j * 4, szA);
            cp_async16(dB + j * 16, srcB + j * 4);
        }
        cp_commit();
    };

    // per-lane ldmatrix addressing (tf32 fragment layout via b16 ldmatrix trick)
    const uint32_t aRowL = (uint32_t)(wm * 64 + ((lane >> 3) & 1) * 8 + (lane & 7));
    const uint32_t aColB = (uint32_t)((lane >> 4) * 16);
    const uint32_t ll = (uint32_t)(lane & 15);
    const uint32_t bRowL = (uint32_t)(wn * 32 + (ll & 7));
    const uint32_t bColB = (uint32_t)(((ll >> 3) & 1) * 16);

    issue_stage(0);

#pragma unroll 1
    for (int it = 0; it < NIT; it++) {
        const int st = it & 1;
        cp_wait<0>();                        // stage it resident
        __syncthreads();                     // also: all warps done with other buffer
        if (it + 1 < NIT) issue_stage(it + 1);   // writes OTHER buffer; lands during compute

        const uint32_t baseA = s0 + (uint32_t)st * STAGE_BYTES;
        const uint32_t baseB = baseA + MAT_BYTES;

#pragma unroll
        for (int ks = 0; ks < 4; ks++) {           // 4 k8-steps per k32 chunk
            const uint32_t kb = (uint32_t)(ks * 32);
            uint32_t bfrag[4][2];
#pragma unroll
            for (int ni = 0; ni < 4; ni++)
                ldsm_x2(bfrag[ni], baseB + (bRowL + ni * 8) * RSB + bColB + kb);

            const uint32_t abase = baseA + aRowL * RSB + aColB + kb;
            uint32_t af0[4], af1[4];
            ldsm_x4(af0, abase);                          // mi=0
            ldsm_x4(af1, abase + 16 * RSB);               // mi=1 prefetch
#pragma unroll
            for (int ni = 0; ni < 4; ni++) mma_tf32(acc[0][ni], af0, bfrag[ni]);
            ldsm_x4(af0, abase + 32 * RSB);               // mi=2 prefetch
#pragma unroll
            for (int ni = 0; ni < 4; ni++) mma_tf32(acc[1][ni], af1, bfrag[ni]);
            ldsm_x4(af1, abase + 48 * RSB);               // mi=3 prefetch
#pragma unroll
            for (int ni = 0; ni < 4; ni++) mma_tf32(acc[2][ni], af0, bfrag[ni]);
#pragma unroll
            for (int ni = 0; ni < 4; ni++) mma_tf32(acc[3][ni], af1, bfrag[ni]);
        }
    }

    // epilogue: c-frag -> C (+bias)
    const int mB = m0 + wm * 64 + (lane >> 2);
    const int nB = n0 + wn * 32 + (lane & 3) * 2;
#pragma unroll
    for (int mi = 0; mi < 4; mi++) {
#pragma unroll
        for (int ni = 0; ni < 4; ni++) {
            const int n = nB + ni * 8;
            float b0 = 0.f, b1 = 0.f;
            if (bias) { b0 = bias[n]; b1 = bias[n + 1]; }
            float* c0 = C + (size_t)(mB + mi * 16) * NTOT + n;
            float* c1 = C + (size_t)(mB + mi * 16 + 8) * NTOT + n;
            *reinterpret_cast<float2*>(c0) =
                make_float2(acc[mi][ni][0] + b0, acc[mi][ni][1] + b1);
            *reinterpret_cast<float2*>(c1) =
                make_float2(acc[mi][ni][2] + b0, acc[mi][ni][3] + b1);
        }
    }
}

// ---------------- LayerNorm over D (emits tf32-rounded output) ---------------
__global__ __launch_bounds__(256) void ln_kernel(const float* __restrict__ gamma,
                                                 const float* __restrict__ beta)
{
    __shared__ float s_sum[8], s_sq[8];
    const int row = blockIdx.x;
    const int t = threadIdx.x;
    const float4* in4 = reinterpret_cast<const float4*>(g_cnn + (size_t)row * DDIM);
    float4 v = in4[t];
    float s = v.x + v.y + v.z + v.w;
    float q = v.x * v.x + v.y * v.y + v.z * v.z + v.w * v.w;
#pragma unroll
    for (int o = 16; o > 0; o >>= 1) {
        s += __shfl_down_sync(0xffffffffu, s, o);
        q += __shfl_down_sync(0xffffffffu, q, o);
    }
    int lane = t & 31, w = t >> 5;
    if (lane == 0) { s_sum[w] = s; s_sq[w] = q; }
    __syncthreads();
    if (t < 32) {
        s = (lane < 8) ? s_sum[lane] : 0.f;
        q = (lane < 8) ? s_sq[lane] : 0.f;
#pragma unroll
        for (int o = 4; o > 0; o >>= 1) {
            s += __shfl_down_sync(0xffffffffu, s, o);
            q += __shfl_down_sync(0xffffffffu, q, o);
        }
        if (lane == 0) { s_sum[0] = s; s_sq[0] = q; }
    }
    __syncthreads();
    float mu = s_sum[0] * (1.f / DDIM);
    float var = s_sq[0] * (1.f / DDIM) - mu * mu;
    float inv = rsqrtf(var + 1e-5f);
    float4 g4 = reinterpret_cast<const float4*>(gamma)[t];
    float4 b4 = reinterpret_cast<const float4*>(beta)[t];
    uint4 o4;
    o4.x = f2tf32((v.x - mu) * inv * g4.x + b4.x);
    o4.y = f2tf32((v.y - mu) * inv * g4.y + b4.y);
    o4.z = f2tf32((v.z - mu) * inv * g4.z + b4.z);
    o4.w = f2tf32((v.w - mu) * inv * g4.w + b4.w);
    reinterpret_cast<uint4*>(g_normed + (size_t)row * DDIM)[t] = o4;
}

// ---------------- SRU scan: cp.async smem-pipelined, 2 steps per round -------
static constexpr int SDEPTH = 16;
static constexpr int STG_FLOATS = 640;   // u 384 | xt 128 | cn 128

__global__ __launch_bounds__(128) void scan_kernel(
    const float* __restrict__ sru_v, const float* __restrict__ sru_b,
    const float* __restrict__ lambda_w, float* __restrict__ out)
{
    __shared__ float ring[SDEPTH * STG_FLOATS];
    const int tid = threadIdx.x;
    const int b = blockIdx.x >> 3;
    const int d0 = (blockIdx.x & 7) * 128;
    const int d = d0 + tid;

    const float vf = sru_v[d],  vr = sru_v[DDIM + d];
    const float bf = sru_b[d],  br = sru_b[DDIM + d];
    const float lam = lambda_w[d];

    const float* Ubase = g_U      + (size_t)b * LDIM * N2   + 3 * d0;
    const float* Nbase = g_normed + (size_t)b * LDIM * DDIM + d0;
    const float* Cbase = g_cnn    + (size_t)b * LDIM * DDIM + d0;
    float*       Obase = out      + (size_t)b * LDIM * DDIM + d0;

    const uint32_t srb = smem_u32(ring);

    auto issue = [&](int l) {
        const uint32_t dst = srb + (uint32_t)(l & (SDEPTH - 1)) * (STG_FLOATS * 4);
        const float* u  = Ubase + (size_t)l * N2;
        if (tid < 96)
            cp_async16(dst + tid * 16, u + tid * 4);
        else
            cp_async16(dst + 1536 + (tid - 96) * 16,
                       Nbase + (size_t)l * DDIM + (tid - 96) * 4);
        if (tid < 32)
            cp_async16(dst + 2048 + tid * 16,
                       Cbase + (size_t)l * DDIM + tid * 4);
    };

    for (int l = 0; l < SDEPTH - 2; l++) { issue(l); cp_commit(); }   // 14 groups

    auto step = [&](int l, float& c) {
        const float* sp = ring + (l & (SDEPTH - 1)) * STG_FLOATS;
        float u0 = sp[3 * tid], u1 = sp[3 * tid + 1], u2 = sp[3 * tid + 2];
        float xt = sp[384 + tid];
        float cn = sp[512 + tid];
        float f = 1.f / (1.f + __expf(-(u1 + vf * c + bf)));
        float cnew = f * c + (1.f - f) * u0;
        float r = 1.f / (1.f + __expf(-(u2 + vr * c + br)));
        float h = r * __tanhf(cnew) + (1.f - r) * xt;
        c = cnew;
        Obase[(size_t)l * DDIM + tid] = lam * cn + (1.f - lam) * h;
    };

    float c = 0.f;
#pragma unroll 1
    for (int l = 0; l < LDIM; l += 2) {
        cp_wait<SDEPTH - 4>();          // stages l and l+1 landed (<=12 remain)
        __syncthreads();                // visibility + prior round's reads done
        if (l + SDEPTH - 2 < LDIM) { issue(l + SDEPTH - 2); cp_commit(); }
        if (l + SDEPTH - 1 < LDIM) { issue(l + SDEPTH - 1); cp_commit(); }
        step(l, c);
        step(l + 1, c);
    }
}

// ---------------- RMSNorm over D, in place on d_out --------------------------
__global__ __launch_bounds__(256) void rms_kernel(float* __restrict__ out,
                                                  const float* __restrict__ wgt)
{
    __shared__ float s_sq[8];
    const int row = blockIdx.x;
    const int t = threadIdx.x;
    float4* p4 = reinterpret_cast<float4*>(out + (size_t)row * DDIM);
    float4 v = p4[t];
    float q = v.x * v.x + v.y * v.y + v.z * v.z + v.w * v.w;
#pragma unroll
    for (int o = 16; o > 0; o >>= 1) q += __shfl_down_sync(0xffffffffu, q, o);
    int lane = t & 31, w = t >> 5;
    if (lane == 0) s_sq[w] = q;
    __syncthreads();
    if (t < 32) {
        q = (lane < 8) ? s_sq[lane] : 0.f;
#pragma unroll
        for (int o = 4; o > 0; o >>= 1) q += __shfl_down_sync(0xffffffffu, q, o);
        if (lane == 0) s_sq[0] = q;
    }
    __syncthreads();
    float inv = rsqrtf(s_sq[0] * (1.f / DDIM) + 1e-6f);
    float4 w4 = reinterpret_cast<const float4*>(wgt)[t];
    float4 o4;
    o4.x = v.x * inv * w4.x;
    o4.y = v.y * inv * w4.y;
    o4.z = v.z * inv * w4.z;
    o4.w = v.w * inv * w4.w;
    p4[t] = o4;
}

// ---------------- launcher ---------------------------------------------------
extern "C" void kernel_launch(void* const* d_in, const int* in_sizes, int n_in,
                              void* d_out, int out_size)
{
    const float* x        = (const float*)d_in[0];
    const float* conv_w   = (const float*)d_in[1];
    const float* conv_b   = (const float*)d_in[2];
    const float* ln_g     = (const float*)d_in[3];
    const float* ln_b     = (const float*)d_in[4];
    const float* sru_w    = (const float*)d_in[5];
    const float* sru_v    = (const float*)d_in[6];
    const float* sru_b    = (const float*)d_in[7];
    const float* lambda_w = (const float*)d_in[8];
    const float* rms_w    = (const float*)d_in[9];
    float* out = (float*)d_out;

    float *p_cnn, *p_normed, *p_U, *p_wc, *p_ws, *p_xr;
    cudaGetSymbolAddress((void**)&p_cnn, g_cnn);
    cudaGetSymbolAddress((void**)&p_normed, g_normed);
    cudaGetSymbolAddress((void**)&p_U, g_U);
    cudaGetSymbolAddress((void**)&p_wc, g_wc);
    cudaGetSymbolAddress((void**)&p_ws, g_ws);
    cudaGetSymbolAddress((void**)&p_xr, g_xr);

    cudaFuncSetAttribute(mma_gemm_kernel<true, N1, K1>,
                         cudaFuncAttributeMaxDynamicSharedMemorySize, GEMM_SMEM);
    cudaFuncSetAttribute(mma_gemm_kernel<false, N2, K2>,
                         cudaFuncAttributeMaxDynamicSharedMemorySize, GEMM_SMEM);

    // 1. repack weights (tf32-rounded) and pre-round x
    repack_conv_kernel<<<(N1 * K1 + 255) / 256, 256>>>(conv_w);
    repack_sru_kernel<<<(N2 * K2 + 255) / 256, 256>>>(sru_w);
    round_x_kernel<<<(MROWS * DDIM / 4 + 255) / 256, 256>>>(x);

    // 2. conv as tensor GEMM: [16384 x 3072] x [3072 x 1024] -> g_cnn
    mma_gemm_kernel<true, N1, K1>
        <<<dim3(N1 / 128, MROWS / 128), 256, GEMM_SMEM>>>(p_xr, p_wc, conv_b, p_cnn);

    // 3. layernorm -> g_normed (tf32-rounded)
    ln_kernel<<<MROWS, 256>>>(ln_g, ln_b);

    // 4. U projection: [16384 x 1024] x [1024 x 3072] -> g_U
    mma_gemm_kernel<false, N2, K2>
        <<<dim3(N2 / 128, MROWS / 128), 256, GEMM_SMEM>>>(p_normed, p_ws, nullptr, p_U);

    // 5. SRU scan + highway mix -> d_out (smem-pipelined, 2 steps/round)
    scan_kernel<<<BDIM * 8, 128>>>(sru_v, sru_b, lambda_w, out);

    // 6. RMSNorm in place on d_out
    rms_kernel<<<MROWS, 256>>>(out, rms_w);
}

// round 15
// speedup vs baseline: 1.0494x; 1.0494x over previous
#include <cuda_runtime.h>
#include <cuda_bf16.h>
#include <math.h>
#include <stdint.h>

#define BDIM 16
#define LDIM 1024
#define DDIM 1024
#define KDIM 3
#define MROWS (BDIM * LDIM)          // 16384
#define N1 DDIM                      // conv GEMM N
#define K1 (KDIM * DDIM)             // conv GEMM K = 3072
#define N2 (3 * DDIM)                // U GEMM N = 3072
#define K2 DDIM                      // U GEMM K = 1024

// ---------------- scratch (allocation-free per harness rules) ----------------
__device__ float g_wc[(size_t)N1 * K1];              // conv weights [o][k*D+i], tf32-rounded
__device__ float g_ws[(size_t)N2 * K2];              // sru weights  [e][kin],  tf32-rounded
__device__ float g_xr[(size_t)MROWS * DDIM];         // x, tf32-rounded
__device__ float g_cnn[(size_t)MROWS * DDIM];        // cnn_out   [b*L+l][D]
__device__ float g_normed[(size_t)MROWS * DDIM];     // layernorm out (tf32-rounded)
__device__ float g_U[(size_t)MROWS * N2];            // SRU preact [b*L+l][3D]

// ======================= small helpers ======================================
__device__ __forceinline__ uint32_t smem_u32(const void* p) {
    uint32_t a;
    asm("{ .reg .u64 t; cvta.to.shared.u64 t, %1; cvt.u32.u64 %0, t; }"
        : "=r"(a) : "l"(p));
    return a;
}
__device__ __forceinline__ void ldsm_x4(uint32_t* r, uint32_t addr) {
    asm volatile("ldmatrix.sync.aligned.m8n8.x4.shared.b16 {%0,%1,%2,%3}, [%4];"
                 : "=r"(r[0]), "=r"(r[1]), "=r"(r[2]), "=r"(r[3]) : "r"(addr));
}
__device__ __forceinline__ void ldsm_x2(uint32_t* r, uint32_t addr) {
    asm volatile("ldmatrix.sync.aligned.m8n8.x2.shared.b16 {%0,%1}, [%2];"
                 : "=r"(r[0]), "=r"(r[1]) : "r"(addr));
}
__device__ __forceinline__ void mma_tf32(float* c, const uint32_t* a, const uint32_t* b) {
    asm volatile("mma.sync.aligned.m16n8k8.row.col.f32.tf32.tf32.f32 "
                 "{%0,%1,%2,%3}, {%4,%5,%6,%7}, {%8,%9}, {%0,%1,%2,%3};"
                 : "+f"(c[0]), "+f"(c[1]), "+f"(c[2]), "+f"(c[3])
                 : "r"(a[0]), "r"(a[1]), "r"(a[2]), "r"(a[3]), "r"(b[0]), "r"(b[1]));
}
__device__ __forceinline__ uint32_t f2tf32(float f) {
    uint32_t r;
    asm("cvt.rna.tf32.f32 %0, %1;" : "=r"(r) : "f"(f));
    return r;
}
__device__ __forceinline__ void cp_async16(uint32_t dst, const void* src) {
    asm volatile("cp.async.cg.shared.global [%0], [%1], 16;"
                 :: "r"(dst), "l"(src) : "memory");
}
__device__ __forceinline__ void cp_commit() {
    asm volatile("cp.async.commit_group;" ::: "memory");
}
template <int N>
__device__ __forceinline__ void cp_wait() {
    asm volatile("cp.async.wait_group %0;" :: "n"(N) : "memory");
}

// ======================= fused prep: repack both weights + round x ===========
__global__ void prep_kernel(const float* __restrict__ conv_w,
                            const float* __restrict__ sru_w,
                            const float* __restrict__ x)
{
    int idx = blockIdx.x * blockDim.x + threadIdx.x;
    if (idx < N1 * K1) {                                  // conv repack
        int o = idx / K1;
        int kk = idx % K1;
        int k = kk >> 10, i = kk & (DDIM - 1);
        float w = conv_w[((size_t)o * DDIM + i) * KDIM + k];
        g_wc[idx] = __uint_as_float(f2tf32(w));
        return;
    }
    idx -= N1 * K1;
    if (idx < N2 * K2) {                                  // sru repack
        int e = idx / K2;
        int kin = idx & (K2 - 1);
        float w = sru_w[(size_t)kin * N2 + e];
        g_ws[idx] = __uint_as_float(f2tf32(w));
        return;
    }
    idx -= N2 * K2;                                       // x round (float4)
    if (idx < MROWS * DDIM / 4) {
        float4 v = reinterpret_cast<const float4*>(x)[idx];
        uint4 t = make_uint4(f2tf32(v.x), f2tf32(v.y), f2tf32(v.z), f2tf32(v.w));
        reinterpret_cast<uint4*>(g_xr)[idx] = t;
    }
}
static constexpr int PREP_TOTAL = N1 * K1 + N2 * K2 + MROWS * DDIM / 4;

// ======================= mma.sync tf32 GEMM (R13, exact) =====================
// C[M,NTOT] = A[M,KTOT] * W^T  (A, W tf32-rounded fp32 in gmem; W [NTOT][KTOT])
// CONV: A virtual — row m=(b*L+l), col kk=(k*D+i) -> xr[(m+k-2)*D+i], 0 if l+k<2
// CTA tile 128x128, K-chunk 32, 8 warps (2m x 4n), warp tile 64x32.
// Register-staged 2-stage buffer; A-fragment ping-pong; ONE barrier per iter.
static constexpr int RSF = 36;                         // floats per smem row (32+4 pad)
static constexpr int RSB = RSF * 4;                    // 144 bytes
static constexpr int MAT_BYTES = 128 * RSB;            // 18432 per matrix
static constexpr int STAGE_BYTES = 2 * MAT_BYTES;      // A + B
static constexpr int GEMM_SMEM = 2 * STAGE_BYTES;      // 73728 B

template <bool CONV, int NTOT, int KTOT>
__global__ void __launch_bounds__(256, 2) mma_gemm_kernel(
    const float* __restrict__ Af,
    const float* __restrict__ W,
    const float* __restrict__ bias, float* __restrict__ C)
{
    extern __shared__ char smem[];
    const uint32_t s0 = smem_u32(smem);

    const int tid = threadIdx.x;
    const int wid = tid >> 5;
    const int lane = tid & 31;
    const int wm = wid >> 2;                 // 0..1
    const int wn = wid & 3;                  // 0..3
    const int m0 = blockIdx.y * 128;
    const int n0 = blockIdx.x * 128;
    constexpr int NIT = KTOT / 32;

    const int lr = tid >> 1;                 // loader row 0..127
    const int colf = (tid & 1) * 16;         // loader col base (floats)

    float acc[4][4][4];
#pragma unroll
    for (int mi = 0; mi < 4; mi++)
#pragma unroll
        for (int ni = 0; ni < 4; ni++)
#pragma unroll
            for (int r = 0; r < 4; r++) acc[mi][ni][r] = 0.f;

    float4 aReg[4];
    float4 bReg[4];

    auto gload = [&](int it) {
        const int kk0 = it * 32;
        if (CONV) {
            const int kblk = kk0 >> 10;                // constant over chunk
            const int i0 = (kk0 & (DDIM - 1)) + colf;
            const int m = m0 + lr;
            const int l = m & (LDIM - 1);
            if (l + kblk >= 2) {
                const float* src = Af + ((size_t)(m + kblk - 2) * DDIM + i0);
#pragma unroll
                for (int j = 0; j < 4; j++)
                    aReg[j] = *reinterpret_cast<const float4*>(src + j * 4);
            } else {
#pragma unroll
                for (int j = 0; j < 4; j++) aReg[j] = make_float4(0.f, 0.f, 0.f, 0.f);
            }
        } else {
            const float* src = Af + (size_t)(m0 + lr) * KTOT + kk0 + colf;
#pragma unroll
            for (int j = 0; j < 4; j++)
                aReg[j] = *reinterpret_cast<const float4*>(src + j * 4);
        }
        const float* bsrc = W + (size_t)(n0 + lr) * KTOT + kk0 + colf;
#pragma unroll
        for (int j = 0; j < 4; j++)
            bReg[j] = *reinterpret_cast<const float4*>(bsrc + j * 4);
    };

    auto sstore = [&](int it) {
        const int st = it & 1;
        char* dA = smem + (size_t)st * STAGE_BYTES;
        char* dB = dA + MAT_BYTES;
#pragma unroll
        for (int j = 0; j < 4; j++) {
            const uint32_t off = (uint32_t)(lr * RSF + colf + j * 4) * 4;
            *reinterpret_cast<float4*>(dA + off) = aReg[j];
            *reinterpret_cast<float4*>(dB + off) = bReg[j];
        }
    };

    // per-lane ldmatrix addressing (tf32 fragment layout via b16 ldmatrix trick)
    const uint32_t aRowL = (uint32_t)(wm * 64 + ((lane >> 3) & 1) * 8 + (lane & 7));
    const uint32_t aColB = (uint32_t)((lane >> 4) * 16);
    const uint32_t ll = (uint32_t)(lane & 15);
    const uint32_t bRowL = (uint32_t)(wn * 32 + (ll & 7));
    const uint32_t bColB = (uint32_t)(((ll >> 3) & 1) * 16);

    gload(0);
    sstore(0);
    __syncthreads();

#pragma unroll 1
    for (int it = 0; it < NIT; it++) {
        const int st = it & 1;
        if (it + 1 < NIT) gload(it + 1);     // LDG latency hides under MMAs

        const uint32_t baseA = s0 + (uint32_t)st * STAGE_BYTES;
        const uint32_t baseB = baseA + MAT_BYTES;

#pragma unroll
        for (int ks = 0; ks < 4; ks++) {           // 4 k8-steps per k32 chunk
            const uint32_t kb = (uint32_t)(ks * 32);
            uint32_t bfrag[4][2];
#pragma unroll
            for (int ni = 0; ni < 4; ni++)
                ldsm_x2(bfrag[ni], baseB + (bRowL + ni * 8) * RSB + bColB + kb);

            const uint32_t abase = baseA + aRowL * RSB + aColB + kb;
            uint32_t af0[4], af1[4];
            ldsm_x4(af0, abase);                          // mi=0
            ldsm_x4(af1, abase + 16 * RSB);               // mi=1 prefetch
#pragma unroll
            for (int ni = 0; ni < 4; ni++) mma_tf32(acc[0][ni], af0, bfrag[ni]);
            ldsm_x4(af0, abase + 32 * RSB);               // mi=2 prefetch
#pragma unroll
            for (int ni = 0; ni < 4; ni++) mma_tf32(acc[1][ni], af1, bfrag[ni]);
            ldsm_x4(af1, abase + 48 * RSB);               // mi=3 prefetch
#pragma unroll
            for (int ni = 0; ni < 4; ni++) mma_tf32(acc[2][ni], af0, bfrag[ni]);
#pragma unroll
            for (int ni = 0; ni < 4; ni++) mma_tf32(acc[3][ni], af1, bfrag[ni]);
        }
        if (it + 1 < NIT) sstore(it + 1);    // pure float4 passthrough tail
        __syncthreads();
    }

    // epilogue: c-frag -> C (+bias)
    const int mB = m0 + wm * 64 + (lane >> 2);
    const int nB = n0 + wn * 32 + (lane & 3) * 2;
#pragma unroll
    for (int mi = 0; mi < 4; mi++) {
#pragma unroll
        for (int ni = 0; ni < 4; ni++) {
            const int n = nB + ni * 8;
            float b0 = 0.f, b1 = 0.f;
            if (bias) { b0 = bias[n]; b1 = bias[n + 1]; }
            float* c0 = C + (size_t)(mB + mi * 16) * NTOT + n;
            float* c1 = C + (size_t)(mB + mi * 16 + 8) * NTOT + n;
            *reinterpret_cast<float2*>(c0) =
                make_float2(acc[mi][ni][0] + b0, acc[mi][ni][1] + b1);
            *reinterpret_cast<float2*>(c1) =
                make_float2(acc[mi][ni][2] + b0, acc[mi][ni][3] + b1);
        }
    }
}

// ---------------- LayerNorm over D (emits tf32-rounded output) ---------------
__global__ __launch_bounds__(256) void ln_kernel(const float* __restrict__ gamma,
                                                 const float* __restrict__ beta)
{
    __shared__ float s_sum[8], s_sq[8];
    const int row = blockIdx.x;
    const int t = threadIdx.x;
    const float4* in4 = reinterpret_cast<const float4*>(g_cnn + (size_t)row * DDIM);
    float4 v = in4[t];
    float s = v.x + v.y + v.z + v.w;
    float q = v.x * v.x + v.y * v.y + v.z * v.z + v.w * v.w;
#pragma unroll
    for (int o = 16; o > 0; o >>= 1) {
        s += __shfl_down_sync(0xffffffffu, s, o);
        q += __shfl_down_sync(0xffffffffu, q, o);
    }
    int lane = t & 31, w = t >> 5;
    if (lane == 0) { s_sum[w] = s; s_sq[w] = q; }
    __syncthreads();
    if (t < 32) {
        s = (lane < 8) ? s_sum[lane] : 0.f;
        q = (lane < 8) ? s_sq[lane] : 0.f;
#pragma unroll
        for (int o = 4; o > 0; o >>= 1) {
            s += __shfl_down_sync(0xffffffffu, s, o);
            q += __shfl_down_sync(0xffffffffu, q, o);
        }
        if (lane == 0) { s_sum[0] = s; s_sq[0] = q; }
    }
    __syncthreads();
    float mu = s_sum[0] * (1.f / DDIM);
    float var = s_sq[0] * (1.f / DDIM) - mu * mu;
    float inv = rsqrtf(var + 1e-5f);
    float4 g4 = reinterpret_cast<const float4*>(gamma)[t];
    float4 b4 = reinterpret_cast<const float4*>(beta)[t];
    uint4 o4;
    o4.x = f2tf32((v.x - mu) * inv * g4.x + b4.x);
    o4.y = f2tf32((v.y - mu) * inv * g4.y + b4.y);
    o4.z = f2tf32((v.z - mu) * inv * g4.z + b4.z);
    o4.w = f2tf32((v.w - mu) * inv * g4.w + b4.w);
    reinterpret_cast<uint4*>(g_normed + (size_t)row * DDIM)[t] = o4;
}

// ---------------- SRU scan: cp.async smem-pipelined, 4 steps per round -------
static constexpr int SDEPTH = 16;
static constexpr int STG_FLOATS = 640;   // u 384 | xt 128 | cn 128

__global__ __launch_bounds__(128) void scan_kernel(
    const float* __restrict__ sru_v, const float* __restrict__ sru_b,
    const float* __restrict__ lambda_w, float* __restrict__ out)
{
    __shared__ float ring[SDEPTH * STG_FLOATS];
    const int tid = threadIdx.x;
    const int b = blockIdx.x >> 3;
    const int d0 = (blockIdx.x & 7) * 128;
    const int d = d0 + tid;

    const float vf = sru_v[d],  vr = sru_v[DDIM + d];
    const float bf = sru_b[d],  br = sru_b[DDIM + d];
    const float lam = lambda_w[d];

    const float* Ubase = g_U      + (size_t)b * LDIM * N2   + 3 * d0;
    const float* Nbase = g_normed + (size_t)b * LDIM * DDIM + d0;
    const float* Cbase = g_cnn    + (size_t)b * LDIM * DDIM + d0;
    float*       Obase = out      + (size_t)b * LDIM * DDIM + d0;

    const uint32_t srb = smem_u32(ring);

    auto issue = [&](int l) {
        const uint32_t dst = srb + (uint32_t)(l & (SDEPTH - 1)) * (STG_FLOATS * 4);
        const float* u  = Ubase + (size_t)l * N2;
        if (tid < 96)
            cp_async16(dst + tid * 16, u + tid * 4);
        else
            cp_async16(dst + 1536 + (tid - 96) * 16,
                       Nbase + (size_t)l * DDIM + (tid - 96) * 4);
        if (tid < 32)
            cp_async16(dst + 2048 + tid * 16,
                       Cbase + (size_t)l * DDIM + tid * 4);
    };

    // prefetch 12 stages (one commit group each)
    for (int l = 0; l < 12; l++) { issue(l); cp_commit(); }

    auto step = [&](int l, float& c) {
        const float* sp = ring + (l & (SDEPTH - 1)) * STG_FLOATS;
        float u0 = sp[3 * tid], u1 = sp[3 * tid + 1], u2 = sp[3 * tid + 2];
        float xt = sp[384 + tid];
        float cn = sp[512 + tid];
        float f = 1.f / (1.f + __expf(-(u1 + vf * c + bf)));
        float cnew = f * c + (1.f - f) * u0;
        float r = 1.f / (1.f + __expf(-(u2 + vr * c + br)));
        float h = r * __tanhf(cnew) + (1.f - r) * xt;
        c = cnew;
        Obase[(size_t)l * DDIM + tid] = lam * cn + (1.f - lam) * h;
    };

    float c = 0.f;
#pragma unroll 1
    for (int l = 0; l < LDIM; l += 4) {
        cp_wait<8>();                   // stages l..l+3 landed (12 outstanding -> 8)
        __syncthreads();                // visibility + prior round's reads done
#pragma unroll
        for (int j = 0; j < 4; j++) {   // refill: targets slots consumed last round
            const int ln = l + 12 + j;
            if (ln < LDIM) { issue(ln); cp_commit(); }
        }
        step(l, c);
        step(l + 1, c);
        step(l + 2, c);
        step(l + 3, c);
    }
}

// ---------------- RMSNorm over D, in place on d_out --------------------------
__global__ __launch_bounds__(256) void rms_kernel(float* __restrict__ out,
                                                  const float* __restrict__ wgt)
{
    __shared__ float s_sq[8];
    const int row = blockIdx.x;
    const int t = threadIdx.x;
    float4* p4 = reinterpret_cast<float4*>(out + (size_t)row * DDIM);
    float4 v = p4[t];
    float q = v.x * v.x + v.y * v.y + v.z * v.z + v.w * v.w;
#pragma unroll
    for (int o = 16; o > 0; o >>= 1) q += __shfl_down_sync(0xffffffffu, q, o);
    int lane = t & 31, w = t >> 5;
    if (lane == 0) s_sq[w] = q;
    __syncthreads();
    if (t < 32) {
        q = (lane < 8) ? s_sq[lane] : 0.f;
#pragma unroll
        for (int o = 4; o > 0; o >>= 1) q += __shfl_down_sync(0xffffffffu, q, o);
        if (lane == 0) s_sq[0] = q;
    }
    __syncthreads();
    float inv = rsqrtf(s_sq[0] * (1.f / DDIM) + 1e-6f);
    float4 w4 = reinterpret_cast<const float4*>(wgt)[t];
    float4 o4;
    o4.x = v.x * inv * w4.x;
    o4.y = v.y * inv * w4.y;
    o4.z = v.z * inv * w4.z;
    o4.w = v.w * inv * w4.w;
    p4[t] = o4;
}

// ---------------- launcher ---------------------------------------------------
extern "C" void kernel_launch(void* const* d_in, const int* in_sizes, int n_in,
                              void* d_out, int out_size)
{
    const float* x        = (const float*)d_in[0];
    const float* conv_w   = (const float*)d_in[1];
    const float* conv_b   = (const float*)d_in[2];
    const float* ln_g     = (const float*)d_in[3];
    const float* ln_b     = (const float*)d_in[4];
    const float* sru_w    = (const float*)d_in[5];
    const float* sru_v    = (const float*)d_in[6];
    const float* sru_b    = (const float*)d_in[7];
    const float* lambda_w = (const float*)d_in[8];
    const float* rms_w    = (const float*)d_in[9];
    float* out = (float*)d_out;

    float *p_cnn, *p_normed, *p_U, *p_wc, *p_ws, *p_xr;
    cudaGetSymbolAddress((void**)&p_cnn, g_cnn);
    cudaGetSymbolAddress((void**)&p_normed, g_normed);
    cudaGetSymbolAddress((void**)&p_U, g_U);
    cudaGetSymbolAddress((void**)&p_wc, g_wc);
    cudaGetSymbolAddress((void**)&p_ws, g_ws);
    cudaGetSymbolAddress((void**)&p_xr, g_xr);

    cudaFuncSetAttribute(mma_gemm_kernel<true, N1, K1>,
                         cudaFuncAttributeMaxDynamicSharedMemorySize, GEMM_SMEM);
    cudaFuncSetAttribute(mma_gemm_kernel<false, N2, K2>,
                         cudaFuncAttributeMaxDynamicSharedMemorySize, GEMM_SMEM);

    // 1. fused prep: repack both weights (tf32) + pre-round x
    prep_kernel<<<(PREP_TOTAL + 255) / 256, 256>>>(conv_w, sru_w, x);

    // 2. conv as tensor GEMM: [16384 x 3072] x [3072 x 1024] -> g_cnn
    mma_gemm_kernel<true, N1, K1>
        <<<dim3(N1 / 128, MROWS / 128), 256, GEMM_SMEM>>>(p_xr, p_wc, conv_b, p_cnn);

    // 3. layernorm -> g_normed (tf32-rounded)
    ln_kernel<<<MROWS, 256>>>(ln_g, ln_b);

    // 4. U projection: [16384 x 1024] x [1024 x 3072] -> g_U
    mma_gemm_kernel<false, N2, K2>
        <<<dim3(N2 / 128, MROWS / 128), 256, GEMM_SMEM>>>(p_normed, p_ws, nullptr, p_U);

    // 5. SRU scan + highway mix -> d_out (smem-pipelined, 4 steps/round)
    scan_kernel<<<BDIM * 8, 128>>>(sru_v, sru_b, lambda_w, out);

    // 6. RMSNorm in place on d_out
    rms_kernel<<<MROWS, 256>>>(out, rms_w);
}

// round 16
// speedup vs baseline: 1.0554x; 1.0058x over previous
#include <cuda_runtime.h>
#include <cuda_bf16.h>
#include <math.h>
#include <stdint.h>

#define BDIM 16
#define LDIM 1024
#define DDIM 1024
#define KDIM 3
#define MROWS (BDIM * LDIM)          // 16384
#define N1 DDIM                      // conv GEMM N
#define K1 (KDIM * DDIM)             // conv GEMM K = 3072
#define N2 (3 * DDIM)                // U GEMM N = 3072
#define K2 DDIM                      // U GEMM K = 1024

// ---------------- scratch (allocation-free per harness rules) ----------------
__device__ float g_wc[(size_t)N1 * K1];              // conv weights [o][k*D+i], tf32-rounded
__device__ float g_ws[(size_t)N2 * K2];              // sru weights  [e][kin],  tf32-rounded
__device__ float g_xr[(size_t)MROWS * DDIM];         // x, tf32-rounded
__device__ float g_cnn[(size_t)MROWS * DDIM];        // cnn_out   [b*L+l][D]
__device__ float g_normed[(size_t)MROWS * DDIM];     // layernorm out (tf32-rounded)
__device__ float g_U[(size_t)MROWS * N2];            // SRU preact [b*L+l][3D]

// ======================= small helpers ======================================
__device__ __forceinline__ uint32_t smem_u32(const void* p) {
    uint32_t a;
    asm("{ .reg .u64 t; cvta.to.shared.u64 t, %1; cvt.u32.u64 %0, t; }"
        : "=r"(a) : "l"(p));
    return a;
}
__device__ __forceinline__ void ldsm_x4(uint32_t* r, uint32_t addr) {
    asm volatile("ldmatrix.sync.aligned.m8n8.x4.shared.b16 {%0,%1,%2,%3}, [%4];"
                 : "=r"(r[0]), "=r"(r[1]), "=r"(r[2]), "=r"(r[3]) : "r"(addr));
}
__device__ __forceinline__ void ldsm_x2(uint32_t* r, uint32_t addr) {
    asm volatile("ldmatrix.sync.aligned.m8n8.x2.shared.b16 {%0,%1}, [%2];"
                 : "=r"(r[0]), "=r"(r[1]) : "r"(addr));
}
__device__ __forceinline__ void mma_tf32(float* c, const uint32_t* a, const uint32_t* b) {
    asm volatile("mma.sync.aligned.m16n8k8.row.col.f32.tf32.tf32.f32 "
                 "{%0,%1,%2,%3}, {%4,%5,%6,%7}, {%8,%9}, {%0,%1,%2,%3};"
                 : "+f"(c[0]), "+f"(c[1]), "+f"(c[2]), "+f"(c[3])
                 : "r"(a[0]), "r"(a[1]), "r"(a[2]), "r"(a[3]), "r"(b[0]), "r"(b[1]));
}
__device__ __forceinline__ uint32_t f2tf32(float f) {
    uint32_t r;
    asm("cvt.rna.tf32.f32 %0, %1;" : "=r"(r) : "f"(f));
    return r;
}
__device__ __forceinline__ void cp_async16(uint32_t dst, const void* src) {
    asm volatile("cp.async.cg.shared.global [%0], [%1], 16;"
                 :: "r"(dst), "l"(src) : "memory");
}
__device__ __forceinline__ void cp_commit() {
    asm volatile("cp.async.commit_group;" ::: "memory");
}
template <int N>
__device__ __forceinline__ void cp_wait() {
    asm volatile("cp.async.wait_group %0;" :: "n"(N) : "memory");
}

// ======================= prep kernels (coalesced) ============================
// conv: g_wc[o][k*D+i] = tf32(conv_w[o][i][k]); one block per o, smem-staged.
__global__ __launch_bounds__(256) void repack_conv_t(const float* __restrict__ conv_w) {
    __shared__ float tile[K1];                 // 3072 floats = [i*3+k]
    const int o = blockIdx.x;
    const int tid = threadIdx.x;
    const float* src = conv_w + (size_t)o * K1;
#pragma unroll
    for (int j = tid; j < K1; j += 256) tile[j] = src[j];
    __syncthreads();
    float* dst = g_wc + (size_t)o * K1;
#pragma unroll
    for (int j = tid; j < K1; j += 256) {
        const int k = j >> 10, i = j & (DDIM - 1);
        dst[j] = __uint_as_float(f2tf32(tile[i * KDIM + k]));
    }
}
// sru: g_ws[e][kin] = tf32(sru_w[kin][e]); 32x32 smem tile transpose.
__global__ __launch_bounds__(256) void repack_sru_t(const float* __restrict__ sru_w) {
    __shared__ float tile[32][33];
    const int tx = threadIdx.x;                // 0..31
    const int ty = threadIdx.y;                // 0..7
    const int e0 = blockIdx.x * 32;
    const int k0 = blockIdx.y * 32;
#pragma unroll
    for (int r = ty; r < 32; r += 8)
        tile[r][tx] = sru_w[(size_t)(k0 + r) * N2 + e0 + tx];
    __syncthreads();
#pragma unroll
    for (int r = ty; r < 32; r += 8)
        g_ws[(size_t)(e0 + r) * K2 + k0 + tx] =
            __uint_as_float(f2tf32(tile[tx][r]));
}
__global__ __launch_bounds__(256) void round_x_kernel(const float* __restrict__ x) {
    int idx = blockIdx.x * blockDim.x + threadIdx.x;
    float4 v = reinterpret_cast<const float4*>(x)[idx];
    uint4 t = make_uint4(f2tf32(v.x), f2tf32(v.y), f2tf32(v.z), f2tf32(v.w));
    reinterpret_cast<uint4*>(g_xr)[idx] = t;
}

// ======================= mma.sync tf32 GEMM (R13, exact) =====================
// C[M,NTOT] = A[M,KTOT] * W^T  (A, W tf32-rounded fp32 in gmem; W [NTOT][KTOT])
// CONV: A virtual — row m=(b*L+l), col kk=(k*D+i) -> xr[(m+k-2)*D+i], 0 if l+k<2
// CTA tile 128x128, K-chunk 32, 8 warps (2m x 4n), warp tile 64x32.
// Register-staged 2-stage buffer; A-fragment ping-pong; ONE barrier per iter.
static constexpr int RSF = 36;                         // floats per smem row (32+4 pad)
static constexpr int RSB = RSF * 4;                    // 144 bytes
static constexpr int MAT_BYTES = 128 * RSB;            // 18432 per matrix
static constexpr int STAGE_BYTES = 2 * MAT_BYTES;      // A + B
static constexpr int GEMM_SMEM = 2 * STAGE_BYTES;      // 73728 B

template <bool CONV, int NTOT, int KTOT>
__global__ void __launch_bounds__(256, 2) mma_gemm_kernel(
    const float* __restrict__ Af,
    const float* __restrict__ W,
    const float* __restrict__ bias, float* __restrict__ C)
{
    extern __shared__ char smem[];
    const uint32_t s0 = smem_u32(smem);

    const int tid = threadIdx.x;
    const int wid = tid >> 5;
    const int lane = tid & 31;
    const int wm = wid >> 2;                 // 0..1
    const int wn = wid & 3;                  // 0..3
    const int m0 = blockIdx.y * 128;
    const int n0 = blockIdx.x * 128;
    constexpr int NIT = KTOT / 32;

    const int lr = tid >> 1;                 // loader row 0..127
    const int colf = (tid & 1) * 16;         // loader col base (floats)

    float acc[4][4][4];
#pragma unroll
    for (int mi = 0; mi < 4; mi++)
#pragma unroll
        for (int ni = 0; ni < 4; ni++)
#pragma unroll
            for (int r = 0; r < 4; r++) acc[mi][ni][r] = 0.f;

    float4 aReg[4];
    float4 bReg[4];

    auto gload = [&](int it) {
        const int kk0 = it * 32;
        if (CONV) {
            const int kblk = kk0 >> 10;                // constant over chunk
            const int i0 = (kk0 & (DDIM - 1)) + colf;
            const int m = m0 + lr;
            const int l = m & (LDIM - 1);
            if (l + kblk >= 2) {
                const float* src = Af + ((size_t)(m + kblk - 2) * DDIM + i0);
#pragma unroll
                for (int j = 0; j < 4; j++)
                    aReg[j] = *reinterpret_cast<const float4*>(src + j * 4);
            } else {
#pragma unroll
                for (int j = 0; j < 4; j++) aReg[j] = make_float4(0.f, 0.f, 0.f, 0.f);
            }
        } else {
            const float* src = Af + (size_t)(m0 + lr) * KTOT + kk0 + colf;
#pragma unroll
            for (int j = 0; j < 4; j++)
                aReg[j] = *reinterpret_cast<const float4*>(src + j * 4);
        }
        const float* bsrc = W + (size_t)(n0 + lr) * KTOT + kk0 + colf;
#pragma unroll
        for (int j = 0; j < 4; j++)
            bReg[j] = *reinterpret_cast<const float4*>(bsrc + j * 4);
    };

    auto sstore = [&](int it) {
        const int st = it & 1;
        char* dA = smem + (size_t)st * STAGE_BYTES;
        char* dB = dA + MAT_BYTES;
#pragma unroll
        for (int j = 0; j < 4; j++) {
            const uint32_t off = (uint32_t)(lr * RSF + colf + j * 4) * 4;
            *reinterpret_cast<float4*>(dA + off) = aReg[j];
            *reinterpret_cast<float4*>(dB + off) = bReg[j];
        }
    };

    // per-lane ldmatrix addressing (tf32 fragment layout via b16 ldmatrix trick)
    const uint32_t aRowL = (uint32_t)(wm * 64 + ((lane >> 3) & 1) * 8 + (lane & 7));
    const uint32_t aColB = (uint32_t)((lane >> 4) * 16);
    const uint32_t ll = (uint32_t)(lane & 15);
    const uint32_t bRowL = (uint32_t)(wn * 32 + (ll & 7));
    const uint32_t bColB = (uint32_t)(((ll >> 3) & 1) * 16);

    gload(0);
    sstore(0);
    __syncthreads();

#pragma unroll 1
    for (int it = 0; it < NIT; it++) {
        const int st = it & 1;
        if (it + 1 < NIT) gload(it + 1);     // LDG latency hides under MMAs

        const uint32_t baseA = s0 + (uint32_t)st * STAGE_BYTES;
        const uint32_t baseB = baseA + MAT_BYTES;

#pragma unroll
        for (int ks = 0; ks < 4; ks++) {           // 4 k8-steps per k32 chunk
            const uint32_t kb = (uint32_t)(ks * 32);
            uint32_t bfrag[4][2];
#pragma unroll
            for (int ni = 0; ni < 4; ni++)
                ldsm_x2(bfrag[ni], baseB + (bRowL + ni * 8) * RSB + bColB + kb);

            const uint32_t abase = baseA + aRowL * RSB + aColB + kb;
            uint32_t af0[4], af1[4];
            ldsm_x4(af0, abase);                          // mi=0
            ldsm_x4(af1, abase + 16 * RSB);               // mi=1 prefetch
#pragma unroll
            for (int ni = 0; ni < 4; ni++) mma_tf32(acc[0][ni], af0, bfrag[ni]);
            ldsm_x4(af0, abase + 32 * RSB);               // mi=2 prefetch
#pragma unroll
            for (int ni = 0; ni < 4; ni++) mma_tf32(acc[1][ni], af1, bfrag[ni]);
            ldsm_x4(af1, abase + 48 * RSB);               // mi=3 prefetch
#pragma unroll
            for (int ni = 0; ni < 4; ni++) mma_tf32(acc[2][ni], af0, bfrag[ni]);
#pragma unroll
            for (int ni = 0; ni < 4; ni++) mma_tf32(acc[3][ni], af1, bfrag[ni]);
        }
        if (it + 1 < NIT) sstore(it + 1);    // pure float4 passthrough tail
        __syncthreads();
    }

    // epilogue: c-frag -> C (+bias)
    const int mB = m0 + wm * 64 + (lane >> 2);
    const int nB = n0 + wn * 32 + (lane & 3) * 2;
#pragma unroll
    for (int mi = 0; mi < 4; mi++) {
#pragma unroll
        for (int ni = 0; ni < 4; ni++) {
            const int n = nB + ni * 8;
            float b0 = 0.f, b1 = 0.f;
            if (bias) { b0 = bias[n]; b1 = bias[n + 1]; }
            float* c0 = C + (size_t)(mB + mi * 16) * NTOT + n;
            float* c1 = C + (size_t)(mB + mi * 16 + 8) * NTOT + n;
            *reinterpret_cast<float2*>(c0) =
                make_float2(acc[mi][ni][0] + b0, acc[mi][ni][1] + b1);
            *reinterpret_cast<float2*>(c1) =
                make_float2(acc[mi][ni][2] + b0, acc[mi][ni][3] + b1);
        }
    }
}

// ---------------- LayerNorm over D (emits tf32-rounded output) ---------------
__global__ __launch_bounds__(256) void ln_kernel(const float* __restrict__ gamma,
                                                 const float* __restrict__ beta)
{
    __shared__ float s_sum[8], s_sq[8];
    const int row = blockIdx.x;
    const int t = threadIdx.x;
    const float4* in4 = reinterpret_cast<const float4*>(g_cnn + (size_t)row * DDIM);
    float4 v = in4[t];
    float s = v.x + v.y + v.z + v.w;
    float q = v.x * v.x + v.y * v.y + v.z * v.z + v.w * v.w;
#pragma unroll
    for (int o = 16; o > 0; o >>= 1) {
        s += __shfl_down_sync(0xffffffffu, s, o);
        q += __shfl_down_sync(0xffffffffu, q, o);
    }
    int lane = t & 31, w = t >> 5;
    if (lane == 0) { s_sum[w] = s; s_sq[w] = q; }
    __syncthreads();
    if (t < 32) {
        s = (lane < 8) ? s_sum[lane] : 0.f;
        q = (lane < 8) ? s_sq[lane] : 0.f;
#pragma unroll
        for (int o = 4; o > 0; o >>= 1) {
            s += __shfl_down_sync(0xffffffffu, s, o);
            q += __shfl_down_sync(0xffffffffu, q, o);
        }
        if (lane == 0) { s_sum[0] = s; s_sq[0] = q; }
    }
    __syncthreads();
    float mu = s_sum[0] * (1.f / DDIM);
    float var = s_sq[0] * (1.f / DDIM) - mu * mu;
    float inv = rsqrtf(var + 1e-5f);
    float4 g4 = reinterpret_cast<const float4*>(gamma)[t];
    float4 b4 = reinterpret_cast<const float4*>(beta)[t];
    uint4 o4;
    o4.x = f2tf32((v.x - mu) * inv * g4.x + b4.x);
    o4.y = f2tf32((v.y - mu) * inv * g4.y + b4.y);
    o4.z = f2tf32((v.z - mu) * inv * g4.z + b4.z);
    o4.w = f2tf32((v.w - mu) * inv * g4.w + b4.w);
    reinterpret_cast<uint4*>(g_normed + (size_t)row * DDIM)[t] = o4;
}

// ---------------- SRU scan: cp.async smem-pipelined, 4 steps per round -------
static constexpr int SDEPTH = 16;
static constexpr int STG_FLOATS = 640;   // u 384 | xt 128 | cn 128

__global__ __launch_bounds__(128) void scan_kernel(
    const float* __restrict__ sru_v, const float* __restrict__ sru_b,
    const float* __restrict__ lambda_w, float* __restrict__ out)
{
    __shared__ float ring[SDEPTH * STG_FLOATS];
    const int tid = threadIdx.x;
    const int b = blockIdx.x >> 3;
    const int d0 = (blockIdx.x & 7) * 128;
    const int d = d0 + tid;

    const float vf = sru_v[d],  vr = sru_v[DDIM + d];
    const float bf = sru_b[d],  br = sru_b[DDIM + d];
    const float lam = lambda_w[d];

    const float* Ubase = g_U      + (size_t)b * LDIM * N2   + 3 * d0;
    const float* Nbase = g_normed + (size_t)b * LDIM * DDIM + d0;
    const float* Cbase = g_cnn    + (size_t)b * LDIM * DDIM + d0;
    float*       Obase = out      + (size_t)b * LDIM * DDIM + d0;

    const uint32_t srb = smem_u32(ring);

    auto issue = [&](int l) {
        const uint32_t dst = srb + (uint32_t)(l & (SDEPTH - 1)) * (STG_FLOATS * 4);
        const float* u  = Ubase + (size_t)l * N2;
        if (tid < 96)
            cp_async16(dst + tid * 16, u + tid * 4);
        else
            cp_async16(dst + 1536 + (tid - 96) * 16,
                       Nbase + (size_t)l * DDIM + (tid - 96) * 4);
        if (tid < 32)
            cp_async16(dst + 2048 + tid * 16,
                       Cbase + (size_t)l * DDIM + tid * 4);
    };

    // prefetch 12 stages (one commit group each)
    for (int l = 0; l < 12; l++) { issue(l); cp_commit(); }

    auto step = [&](int l, float& c) {
        const float* sp = ring + (l & (SDEPTH - 1)) * STG_FLOATS;
        float u0 = sp[3 * tid], u1 = sp[3 * tid + 1], u2 = sp[3 * tid + 2];
        float xt = sp[384 + tid];
        float cn = sp[512 + tid];
        float f = 1.f / (1.f + __expf(-(u1 + vf * c + bf)));
        float cnew = f * c + (1.f - f) * u0;
        float r = 1.f / (1.f + __expf(-(u2 + vr * c + br)));
        float h = r * __tanhf(cnew) + (1.f - r) * xt;
        c = cnew;
        Obase[(size_t)l * DDIM + tid] = lam * cn + (1.f - lam) * h;
    };

    float c = 0.f;
#pragma unroll 1
    for (int l = 0; l < LDIM; l += 4) {
        cp_wait<8>();                   // stages l..l+3 landed (12 outstanding -> 8)
        __syncthreads();                // visibility + prior round's reads done
#pragma unroll
        for (int j = 0; j < 4; j++) {   // refill: targets slots consumed last round
            const int ln = l + 12 + j;
            if (ln < LDIM) { issue(ln); cp_commit(); }
        }
        step(l, c);
        step(l + 1, c);
        step(l + 2, c);
        step(l + 3, c);
    }
}

// ---------------- RMSNorm over D, in place on d_out --------------------------
__global__ __launch_bounds__(256) void rms_kernel(float* __restrict__ out,
                                                  const float* __restrict__ wgt)
{
    __shared__ float s_sq[8];
    const int row = blockIdx.x;
    const int t = threadIdx.x;
    float4* p4 = reinterpret_cast<float4*>(out + (size_t)row * DDIM);
    float4 v = p4[t];
    float q = v.x * v.x + v.y * v.y + v.z * v.z + v.w * v.w;
#pragma unroll
    for (int o = 16; o > 0; o >>= 1) q += __shfl_down_sync(0xffffffffu, q, o);
    int lane = t & 31, w = t >> 5;
    if (lane == 0) s_sq[w] = q;
    __syncthreads();
    if (t < 32) {
        q = (lane < 8) ? s_sq[lane] : 0.f;
#pragma unroll
        for (int o = 4; o > 0; o >>= 1) q += __shfl_down_sync(0xffffffffu, q, o);
        if (lane == 0) s_sq[0] = q;
    }
    __syncthreads();
    float inv = rsqrtf(s_sq[0] * (1.f / DDIM) + 1e-6f);
    float4 w4 = reinterpret_cast<const float4*>(wgt)[t];
    float4 o4;
    o4.x = v.x * inv * w4.x;
    o4.y = v.y * inv * w4.y;
    o4.z = v.z * inv * w4.z;
    o4.w = v.w * inv * w4.w;
    p4[t] = o4;
}

// ---------------- launcher ---------------------------------------------------
extern "C" void kernel_launch(void* const* d_in, const int* in_sizes, int n_in,
                              void* d_out, int out_size)
{
    const float* x        = (const float*)d_in[0];
    const float* conv_w   = (const float*)d_in[1];
    const float* conv_b   = (const float*)d_in[2];
    const float* ln_g     = (const float*)d_in[3];
    const float* ln_b     = (const float*)d_in[4];
    const float* sru_w    = (const float*)d_in[5];
    const float* sru_v    = (const float*)d_in[6];
    const float* sru_b    = (const float*)d_in[7];
    const float* lambda_w = (const float*)d_in[8];
    const float* rms_w    = (const float*)d_in[9];
    float* out = (float*)d_out;

    float *p_cnn, *p_normed, *p_U, *p_wc, *p_ws, *p_xr;
    cudaGetSymbolAddress((void**)&p_cnn, g_cnn);
    cudaGetSymbolAddress((void**)&p_normed, g_normed);
    cudaGetSymbolAddress((void**)&p_U, g_U);
    cudaGetSymbolAddress((void**)&p_wc, g_wc);
    cudaGetSymbolAddress((void**)&p_ws, g_ws);
    cudaGetSymbolAddress((void**)&p_xr, g_xr);

    cudaFuncSetAttribute(mma_gemm_kernel<true, N1, K1>,
                         cudaFuncAttributeMaxDynamicSharedMemorySize, GEMM_SMEM);
    cudaFuncSetAttribute(mma_gemm_kernel<false, N2, K2>,
                         cudaFuncAttributeMaxDynamicSharedMemorySize, GEMM_SMEM);

    // 1. prep: coalesced transpose repacks + x pre-round
    repack_conv_t<<<N1, 256>>>(conv_w);
    repack_sru_t<<<dim3(N2 / 32, K2 / 32), dim3(32, 8)>>>(sru_w);
    round_x_kernel<<<(MROWS * DDIM / 4 + 255) / 256, 256>>>(x);

    // 2. conv as tensor GEMM: [16384 x 3072] x [3072 x 1024] -> g_cnn
    mma_gemm_kernel<true, N1, K1>
        <<<dim3(N1 / 128, MROWS / 128), 256, GEMM_SMEM>>>(p_xr, p_wc, conv_b, p_cnn);

    // 3. layernorm -> g_normed (tf32-rounded)
    ln_kernel<<<MROWS, 256>>>(ln_g, ln_b);

    // 4. U projection: [16384 x 1024] x [1024 x 3072] -> g_U
    mma_gemm_kernel<false, N2, K2>
        <<<dim3(N2 / 128, MROWS / 128), 256, GEMM_SMEM>>>(p_normed, p_ws, nullptr, p_U);

    // 5. SRU scan + highway mix -> d_out (smem-pipelined, 4 steps/round)
    scan_kernel<<<BDIM * 8, 128>>>(sru_v, sru_b, lambda_w, out);

    // 6. RMSNorm in place on d_out
    rms_kernel<<<MROWS, 256>>>(out, rms_w);
}

// round 17
// speedup vs baseline: 1.1194x; 1.0606x over previous
#include <cuda_runtime.h>
#include <cuda_bf16.h>
#include <math.h>
#include <stdint.h>

#define BDIM 16
#define LDIM 1024
#define DDIM 1024
#define KDIM 3
#define MROWS (BDIM * LDIM)          // 16384
#define N1 DDIM                      // conv GEMM N
#define K1 (KDIM * DDIM)             // conv GEMM K = 3072
#define N2 (3 * DDIM)                // U GEMM N = 3072
#define K2 DDIM                      // U GEMM K = 1024

// ---------------- scratch (allocation-free per harness rules) ----------------
__device__ float g_wc[(size_t)N1 * K1];              // conv weights [o][k*D+i], tf32-rounded
__device__ float g_ws[(size_t)N2 * K2];              // sru weights  [e][kin],  tf32-rounded
__device__ float g_xr[(size_t)MROWS * DDIM];         // x, tf32-rounded
__device__ float g_cnn[(size_t)MROWS * DDIM];        // cnn_out   [b*L+l][D]
__device__ float g_normed[(size_t)MROWS * DDIM];     // layernorm out (tf32-rounded)
__device__ float g_U[(size_t)MROWS * N2];            // SRU preact [b*L+l][3D]

// ======================= small helpers ======================================
__device__ __forceinline__ uint32_t smem_u32(const void* p) {
    uint32_t a;
    asm("{ .reg .u64 t; cvta.to.shared.u64 t, %1; cvt.u32.u64 %0, t; }"
        : "=r"(a) : "l"(p));
    return a;
}
__device__ __forceinline__ void ldsm_x4(uint32_t* r, uint32_t addr) {
    asm volatile("ldmatrix.sync.aligned.m8n8.x4.shared.b16 {%0,%1,%2,%3}, [%4];"
                 : "=r"(r[0]), "=r"(r[1]), "=r"(r[2]), "=r"(r[3]) : "r"(addr));
}
__device__ __forceinline__ void ldsm_x2(uint32_t* r, uint32_t addr) {
    asm volatile("ldmatrix.sync.aligned.m8n8.x2.shared.b16 {%0,%1}, [%2];"
                 : "=r"(r[0]), "=r"(r[1]) : "r"(addr));
}
__device__ __forceinline__ void mma_tf32(float* c, const uint32_t* a, const uint32_t* b) {
    asm volatile("mma.sync.aligned.m16n8k8.row.col.f32.tf32.tf32.f32 "
                 "{%0,%1,%2,%3}, {%4,%5,%6,%7}, {%8,%9}, {%0,%1,%2,%3};"
                 : "+f"(c[0]), "+f"(c[1]), "+f"(c[2]), "+f"(c[3])
                 : "r"(a[0]), "r"(a[1]), "r"(a[2]), "r"(a[3]), "r"(b[0]), "r"(b[1]));
}
__device__ __forceinline__ uint32_t f2tf32(float f) {
    uint32_t r;
    asm("cvt.rna.tf32.f32 %0, %1;" : "=r"(r) : "f"(f));
    return r;
}
__device__ __forceinline__ void cp_async16(uint32_t dst, const void* src) {
    asm volatile("cp.async.cg.shared.global [%0], [%1], 16;"
                 :: "r"(dst), "l"(src) : "memory");
}
__device__ __forceinline__ void cp_commit() {
    asm volatile("cp.async.commit_group;" ::: "memory");
}
template <int N>
__device__ __forceinline__ void cp_wait() {
    asm volatile("cp.async.wait_group %0;" :: "n"(N) : "memory");
}

// ======================= prep kernels (coalesced) ============================
__global__ __launch_bounds__(256) void repack_conv_t(const float* __restrict__ conv_w) {
    __shared__ float tile[K1];                 // 3072 floats = [i*3+k]
    const int o = blockIdx.x;
    const int tid = threadIdx.x;
    const float* src = conv_w + (size_t)o * K1;
#pragma unroll
    for (int j = tid; j < K1; j += 256) tile[j] = src[j];
    __syncthreads();
    float* dst = g_wc + (size_t)o * K1;
#pragma unroll
    for (int j = tid; j < K1; j += 256) {
        const int k = j >> 10, i = j & (DDIM - 1);
        dst[j] = __uint_as_float(f2tf32(tile[i * KDIM + k]));
    }
}
__global__ __launch_bounds__(256) void repack_sru_t(const float* __restrict__ sru_w) {
    __shared__ float tile[32][33];
    const int tx = threadIdx.x;                // 0..31
    const int ty = threadIdx.y;                // 0..7
    const int e0 = blockIdx.x * 32;
    const int k0 = blockIdx.y * 32;
#pragma unroll
    for (int r = ty; r < 32; r += 8)
        tile[r][tx] = sru_w[(size_t)(k0 + r) * N2 + e0 + tx];
    __syncthreads();
#pragma unroll
    for (int r = ty; r < 32; r += 8)
        g_ws[(size_t)(e0 + r) * K2 + k0 + tx] =
            __uint_as_float(f2tf32(tile[tx][r]));
}
__global__ __launch_bounds__(256) void round_x_kernel(const float* __restrict__ x) {
    int idx = blockIdx.x * blockDim.x + threadIdx.x;
    float4 v = reinterpret_cast<const float4*>(x)[idx];
    uint4 t = make_uint4(f2tf32(v.x), f2tf32(v.y), f2tf32(v.z), f2tf32(v.w));
    reinterpret_cast<uint4*>(g_xr)[idx] = t;
}

// ======================= mma.sync tf32 GEMM (R13, exact) =====================
static constexpr int RSF = 36;                         // floats per smem row (32+4 pad)
static constexpr int RSB = RSF * 4;                    // 144 bytes
static constexpr int MAT_BYTES = 128 * RSB;            // 18432 per matrix
static constexpr int STAGE_BYTES = 2 * MAT_BYTES;      // A + B
static constexpr int GEMM_SMEM = 2 * STAGE_BYTES;      // 73728 B

template <bool CONV, int NTOT, int KTOT>
__global__ void __launch_bounds__(256, 2) mma_gemm_kernel(
    const float* __restrict__ Af,
    const float* __restrict__ W,
    const float* __restrict__ bias, float* __restrict__ C)
{
    extern __shared__ char smem[];
    const uint32_t s0 = smem_u32(smem);

    const int tid = threadIdx.x;
    const int wid = tid >> 5;
    const int lane = tid & 31;
    const int wm = wid >> 2;                 // 0..1
    const int wn = wid & 3;                  // 0..3
    const int m0 = blockIdx.y * 128;
    const int n0 = blockIdx.x * 128;
    constexpr int NIT = KTOT / 32;

    const int lr = tid >> 1;                 // loader row 0..127
    const int colf = (tid & 1) * 16;         // loader col base (floats)

    float acc[4][4][4];
#pragma unroll
    for (int mi = 0; mi < 4; mi++)
#pragma unroll
        for (int ni = 0; ni < 4; ni++)
#pragma unroll
            for (int r = 0; r < 4; r++) acc[mi][ni][r] = 0.f;

    float4 aReg[4];
    float4 bReg[4];

    auto gload = [&](int it) {
        const int kk0 = it * 32;
        if (CONV) {
            const int kblk = kk0 >> 10;                // constant over chunk
            const int i0 = (kk0 & (DDIM - 1)) + colf;
            const int m = m0 + lr;
            const int l = m & (LDIM - 1);
            if (l + kblk >= 2) {
                const float* src = Af + ((size_t)(m + kblk - 2) * DDIM + i0);
#pragma unroll
                for (int j = 0; j < 4; j++)
                    aReg[j] = *reinterpret_cast<const float4*>(src + j * 4);
            } else {
#pragma unroll
                for (int j = 0; j < 4; j++) aReg[j] = make_float4(0.f, 0.f, 0.f, 0.f);
            }
        } else {
            const float* src = Af + (size_t)(m0 + lr) * KTOT + kk0 + colf;
#pragma unroll
            for (int j = 0; j < 4; j++)
                aReg[j] = *reinterpret_cast<const float4*>(src + j * 4);
        }
        const float* bsrc = W + (size_t)(n0 + lr) * KTOT + kk0 + colf;
#pragma unroll
        for (int j = 0; j < 4; j++)
            bReg[j] = *reinterpret_cast<const float4*>(bsrc + j * 4);
    };

    auto sstore = [&](int it) {
        const int st = it & 1;
        char* dA = smem + (size_t)st * STAGE_BYTES;
        char* dB = dA + MAT_BYTES;
#pragma unroll
        for (int j = 0; j < 4; j++) {
            const uint32_t off = (uint32_t)(lr * RSF + colf + j * 4) * 4;
            *reinterpret_cast<float4*>(dA + off) = aReg[j];
            *reinterpret_cast<float4*>(dB + off) = bReg[j];
        }
    };

    // per-lane ldmatrix addressing (tf32 fragment layout via b16 ldmatrix trick)
    const uint32_t aRowL = (uint32_t)(wm * 64 + ((lane >> 3) & 1) * 8 + (lane & 7));
    const uint32_t aColB = (uint32_t)((lane >> 4) * 16);
    const uint32_t ll = (uint32_t)(lane & 15);
    const uint32_t bRowL = (uint32_t)(wn * 32 + (ll & 7));
    const uint32_t bColB = (uint32_t)(((ll >> 3) & 1) * 16);

    gload(0);
    sstore(0);
    __syncthreads();

#pragma unroll 1
    for (int it = 0; it < NIT; it++) {
        const int st = it & 1;
        if (it + 1 < NIT) gload(it + 1);     // LDG latency hides under MMAs

        const uint32_t baseA = s0 + (uint32_t)st * STAGE_BYTES;
        const uint32_t baseB = baseA + MAT_BYTES;

#pragma unroll
        for (int ks = 0; ks < 4; ks++) {           // 4 k8-steps per k32 chunk
            const uint32_t kb = (uint32_t)(ks * 32);
            uint32_t bfrag[4][2];
#pragma unroll
            for (int ni = 0; ni < 4; ni++)
                ldsm_x2(bfrag[ni], baseB + (bRowL + ni * 8) * RSB + bColB + kb);

            const uint32_t abase = baseA + aRowL * RSB + aColB + kb;
            uint32_t af0[4], af1[4];
            ldsm_x4(af0, abase);                          // mi=0
            ldsm_x4(af1, abase + 16 * RSB);               // mi=1 prefetch
#pragma unroll
            for (int ni = 0; ni < 4; ni++) mma_tf32(acc[0][ni], af0, bfrag[ni]);
            ldsm_x4(af0, abase + 32 * RSB);               // mi=2 prefetch
#pragma unroll
            for (int ni = 0; ni < 4; ni++) mma_tf32(acc[1][ni], af1, bfrag[ni]);
            ldsm_x4(af1, abase + 48 * RSB);               // mi=3 prefetch
#pragma unroll
            for (int ni = 0; ni < 4; ni++) mma_tf32(acc[2][ni], af0, bfrag[ni]);
#pragma unroll
            for (int ni = 0; ni < 4; ni++) mma_tf32(acc[3][ni], af1, bfrag[ni]);
        }
        if (it + 1 < NIT) sstore(it + 1);    // pure float4 passthrough tail
        __syncthreads();
    }

    // epilogue: c-frag -> C (+bias)
    const int mB = m0 + wm * 64 + (lane >> 2);
    const int nB = n0 + wn * 32 + (lane & 3) * 2;
#pragma unroll
    for (int mi = 0; mi < 4; mi++) {
#pragma unroll
        for (int ni = 0; ni < 4; ni++) {
            const int n = nB + ni * 8;
            float b0 = 0.f, b1 = 0.f;
            if (bias) { b0 = bias[n]; b1 = bias[n + 1]; }
            float* c0 = C + (size_t)(mB + mi * 16) * NTOT + n;
            float* c1 = C + (size_t)(mB + mi * 16 + 8) * NTOT + n;
            *reinterpret_cast<float2*>(c0) =
                make_float2(acc[mi][ni][0] + b0, acc[mi][ni][1] + b1);
            *reinterpret_cast<float2*>(c1) =
                make_float2(acc[mi][ni][2] + b0, acc[mi][ni][3] + b1);
        }
    }
}

// ---------------- LayerNorm over D (emits tf32-rounded output) ---------------
__global__ __launch_bounds__(256) void ln_kernel(const float* __restrict__ gamma,
                                                 const float* __restrict__ beta)
{
    __shared__ float s_sum[8], s_sq[8];
    const int row = blockIdx.x;
    const int t = threadIdx.x;
    const float4* in4 = reinterpret_cast<const float4*>(g_cnn + (size_t)row * DDIM);
    float4 v = in4[t];
    float s = v.x + v.y + v.z + v.w;
    float q = v.x * v.x + v.y * v.y + v.z * v.z + v.w * v.w;
#pragma unroll
    for (int o = 16; o > 0; o >>= 1) {
        s += __shfl_down_sync(0xffffffffu, s, o);
        q += __shfl_down_sync(0xffffffffu, q, o);
    }
    int lane = t & 31, w = t >> 5;
    if (lane == 0) { s_sum[w] = s; s_sq[w] = q; }
    __syncthreads();
    if (t < 32) {
        s = (lane < 8) ? s_sum[lane] : 0.f;
        q = (lane < 8) ? s_sq[lane] : 0.f;
#pragma unroll
        for (int o = 4; o > 0; o >>= 1) {
            s += __shfl_down_sync(0xffffffffu, s, o);
            q += __shfl_down_sync(0xffffffffu, q, o);
        }
        if (lane == 0) { s_sum[0] = s; s_sq[0] = q; }
    }
    __syncthreads();
    float mu = s_sum[0] * (1.f / DDIM);
    float var = s_sq[0] * (1.f / DDIM) - mu * mu;
    float inv = rsqrtf(var + 1e-5f);
    float4 g4 = reinterpret_cast<const float4*>(gamma)[t];
    float4 b4 = reinterpret_cast<const float4*>(beta)[t];
    uint4 o4;
    o4.x = f2tf32((v.x - mu) * inv * g4.x + b4.x);
    o4.y = f2tf32((v.y - mu) * inv * g4.y + b4.y);
    o4.z = f2tf32((v.z - mu) * inv * g4.z + b4.z);
    o4.w = f2tf32((v.w - mu) * inv * g4.w + b4.w);
    reinterpret_cast<uint4*>(g_normed + (size_t)row * DDIM)[t] = o4;
}

// ---------------- SRU scan: 32-deep ring, 8 steps/round, tanh-sigmoid --------
static constexpr int SDEPTH = 32;
static constexpr int STG_FLOATS = 640;   // u 384 | xt 128 | cn 128
static constexpr int SCAN_SMEM = SDEPTH * STG_FLOATS * 4;   // 81920 B

__global__ __launch_bounds__(128) void scan_kernel(
    const float* __restrict__ sru_v, const float* __restrict__ sru_b,
    const float* __restrict__ lambda_w, float* __restrict__ out)
{
    extern __shared__ float ring[];
    const int tid = threadIdx.x;
    const int b = blockIdx.x >> 3;
    const int d0 = (blockIdx.x & 7) * 128;
    const int d = d0 + tid;

    const float hvf = 0.5f * sru_v[d],  hvr = 0.5f * sru_v[DDIM + d];
    const float hbf = 0.5f * sru_b[d],  hbr = 0.5f * sru_b[DDIM + d];
    const float lam = lambda_w[d];

    const float* Ubase = g_U      + (size_t)b * LDIM * N2   + 3 * d0;
    const float* Nbase = g_normed + (size_t)b * LDIM * DDIM + d0;
    const float* Cbase = g_cnn    + (size_t)b * LDIM * DDIM + d0;
    float*       Obase = out      + (size_t)b * LDIM * DDIM + d0;

    const uint32_t srb = smem_u32(ring);

    auto issue = [&](int l) {
        const uint32_t dst = srb + (uint32_t)(l & (SDEPTH - 1)) * (STG_FLOATS * 4);
        const float* u  = Ubase + (size_t)l * N2;
        if (tid < 96)
            cp_async16(dst + tid * 16, u + tid * 4);
        else
            cp_async16(dst + 1536 + (tid - 96) * 16,
                       Nbase + (size_t)l * DDIM + (tid - 96) * 4);
        if (tid < 32)
            cp_async16(dst + 2048 + tid * 16,
                       Cbase + (size_t)l * DDIM + tid * 4);
    };

    // prefetch 16 stages (one commit group each)
    for (int l = 0; l < 16; l++) { issue(l); cp_commit(); }

    // sigmoid(x) = 0.5*(1+tanh(x/2)); c' = 0.5*(c+u0) + tanh(.)*0.5*(c-u0)
    auto step = [&](int l, float& c) {
        const float* sp = ring + (l & (SDEPTH - 1)) * STG_FLOATS;
        float u0 = sp[3 * tid], u1 = sp[3 * tid + 1], u2 = sp[3 * tid + 2];
        float xt = sp[384 + tid];
        float cn = sp[512 + tid];
        float tf = __tanhf(fmaf(hvf, c, fmaf(0.5f, u1, hbf)));
        float hs = 0.5f * (c + u0);
        float hd = 0.5f * (c - u0);
        float cnew = fmaf(tf, hd, hs);
        float tr = __tanhf(fmaf(hvr, c, fmaf(0.5f, u2, hbr)));
        float r = fmaf(0.5f, tr, 0.5f);
        float h = r * __tanhf(cnew) + (1.f - r) * xt;
        c = cnew;
        Obase[(size_t)l * DDIM + tid] = lam * cn + (1.f - lam) * h;
    };

    float c = 0.f;
#pragma unroll 1
    for (int l = 0; l < LDIM; l += 8) {
        cp_wait<8>();                   // all but last 8 groups landed => l..l+7 ready
        __syncthreads();                // visibility + prior round's reads done
#pragma unroll
        for (int j = 0; j < 8; j++) {   // unconditional commits keep group count exact
            const int ln = l + 16 + j;
            if (ln < LDIM) issue(ln);
            cp_commit();
        }
#pragma unroll
        for (int j = 0; j < 8; j++) step(l + j, c);
    }
}

// ---------------- RMSNorm over D, in place on d_out --------------------------
__global__ __launch_bounds__(256) void rms_kernel(float* __restrict__ out,
                                                  const float* __restrict__ wgt)
{
    __shared__ float s_sq[8];
    const int row = blockIdx.x;
    const int t = threadIdx.x;
    float4* p4 = reinterpret_cast<float4*>(out + (size_t)row * DDIM);
    float4 v = p4[t];
    float q = v.x * v.x + v.y * v.y + v.z * v.z + v.w * v.w;
#pragma unroll
    for (int o = 16; o > 0; o >>= 1) q += __shfl_down_sync(0xffffffffu, q, o);
    int lane = t & 31, w = t >> 5;
    if (lane == 0) s_sq[w] = q;
    __syncthreads();
    if (t < 32) {
        q = (lane < 8) ? s_sq[lane] : 0.f;
#pragma unroll
        for (int o = 4; o > 0; o >>= 1) q += __shfl_down_sync(0xffffffffu, q, o);
        if (lane == 0) s_sq[0] = q;
    }
    __syncthreads();
    float inv = rsqrtf(s_sq[0] * (1.f / DDIM) + 1e-6f);
    float4 w4 = reinterpret_cast<const float4*>(wgt)[t];
    float4 o4;
    o4.x = v.x * inv * w4.x;
    o4.y = v.y * inv * w4.y;
    o4.z = v.z * inv * w4.z;
    o4.w = v.w * inv * w4.w;
    p4[t] = o4;
}

// ---------------- launcher ---------------------------------------------------
extern "C" void kernel_launch(void* const* d_in, const int* in_sizes, int n_in,
                              void* d_out, int out_size)
{
    const float* x        = (const float*)d_in[0];
    const float* conv_w   = (const float*)d_in[1];
    const float* conv_b   = (const float*)d_in[2];
    const float* ln_g     = (const float*)d_in[3];
    const float* ln_b     = (const float*)d_in[4];
    const float* sru_w    = (const float*)d_in[5];
    const float* sru_v    = (const float*)d_in[6];
    const float* sru_b    = (const float*)d_in[7];
    const float* lambda_w = (const float*)d_in[8];
    const float* rms_w    = (const float*)d_in[9];
    float* out = (float*)d_out;

    float *p_cnn, *p_normed, *p_U, *p_wc, *p_ws, *p_xr;
    cudaGetSymbolAddress((void**)&p_cnn, g_cnn);
    cudaGetSymbolAddress((void**)&p_normed, g_normed);
    cudaGetSymbolAddress((void**)&p_U, g_U);
    cudaGetSymbolAddress((void**)&p_wc, g_wc);
    cudaGetSymbolAddress((void**)&p_ws, g_ws);
    cudaGetSymbolAddress((void**)&p_xr, g_xr);

    cudaFuncSetAttribute(mma_gemm_kernel<true, N1, K1>,
                         cudaFuncAttributeMaxDynamicSharedMemorySize, GEMM_SMEM);
    cudaFuncSetAttribute(mma_gemm_kernel<false, N2, K2>,
                         cudaFuncAttributeMaxDynamicSharedMemorySize, GEMM_SMEM);
    cudaFuncSetAttribute(scan_kernel,
                         cudaFuncAttributeMaxDynamicSharedMemorySize, SCAN_SMEM);

    // 1. prep: coalesced transpose repacks + x pre-round
    repack_conv_t<<<N1, 256>>>(conv_w);
    repack_sru_t<<<dim3(N2 / 32, K2 / 32), dim3(32, 8)>>>(sru_w);
    round_x_kernel<<<(MROWS * DDIM / 4 + 255) / 256, 256>>>(x);

    // 2. conv as tensor GEMM: [16384 x 3072] x [3072 x 1024] -> g_cnn
    mma_gemm_kernel<true, N1, K1>
        <<<dim3(N1 / 128, MROWS / 128), 256, GEMM_SMEM>>>(p_xr, p_wc, conv_b, p_cnn);

    // 3. layernorm -> g_normed (tf32-rounded)
    ln_kernel<<<MROWS, 256>>>(ln_g, ln_b);

    // 4. U projection: [16384 x 1024] x [1024 x 3072] -> g_U
    mma_gemm_kernel<false, N2, K2>
        <<<dim3(N2 / 128, MROWS / 128), 256, GEMM_SMEM>>>(p_normed, p_ws, nullptr, p_U);

    // 5. SRU scan + highway mix -> d_out (32-deep ring, 8 steps/round)
    scan_kernel<<<BDIM * 8, 128, SCAN_SMEM>>>(sru_v, sru_b, lambda_w, out);

    // 6. RMSNorm in place on d_out
    rms_kernel<<<MROWS, 256>>>(out, rms_w);
}